// round 1
// baseline (speedup 1.0000x reference)
#include <cuda_runtime.h>
#include <math.h>

#define B_  64
#define T_  218
#define D_  512
#define R_  (B_*T_)      // 13952 = 109*128
#define H_  4
#define DK_ 128
#define QKVW (3*D_)      // 1536

// ---------------- scratch (device globals; no allocations allowed) ----------
__device__ float g_h[R_*D_];                 // LN output (reused for both LNs)
__device__ float g_qkv[R_*QKVW];             // qkv
__device__ float g_fsmn[R_*D_];              // fsmn branch
__device__ float g_scores[B_*H_*T_*T_];      // attention scores / probs
__device__ float g_ctx[R_*D_];               // attention context
__device__ float g_x1[R_*D_];                // x after attention block
__device__ float g_mid[R_*2048];             // ffn hidden
__device__ float g_kw[11*D_*D_];             // fsmn weights transposed [tap][din][dout]

// ---------------- fsmn weight transpose ------------------------------------
__global__ void kw_transpose(const float* __restrict__ fw) {
    int idx = blockIdx.x * 256 + threadIdx.x;
    if (idx >= 11 * D_ * D_) return;
    int tap  = idx / (D_ * D_);
    int rem  = idx % (D_ * D_);
    int din  = rem / D_;
    int dout = rem % D_;
    g_kw[idx] = fw[((size_t)dout * D_ + din) * 11 + tap];
}

// ---------------- layer norm (one block per row, 128 threads) --------------
__global__ void ln_kernel(const float* __restrict__ x, const float* __restrict__ w,
                          const float* __restrict__ b, float* __restrict__ out) {
    int row = blockIdx.x;
    const float* xr = x + (size_t)row * D_;
    float* orow = out + (size_t)row * D_;
    float v[4];
    float s = 0.f, sq = 0.f;
#pragma unroll
    for (int i = 0; i < 4; i++) {
        v[i] = xr[threadIdx.x + i * 128];
        s += v[i]; sq += v[i] * v[i];
    }
    __shared__ float sm[8];
#pragma unroll
    for (int o = 16; o; o >>= 1) {
        s  += __shfl_xor_sync(~0u, s, o);
        sq += __shfl_xor_sync(~0u, sq, o);
    }
    int lane = threadIdx.x & 31, wid = threadIdx.x >> 5;
    if (lane == 0) { sm[wid] = s; sm[4 + wid] = sq; }
    __syncthreads();
    if (threadIdx.x == 0) {
        float S  = sm[0] + sm[1] + sm[2] + sm[3];
        float SQ = sm[4] + sm[5] + sm[6] + sm[7];
        float mean = S * (1.f / D_);
        float var  = SQ * (1.f / D_) - mean * mean;
        sm[0] = mean;
        sm[1] = rsqrtf(var + 1e-5f);
    }
    __syncthreads();
    float mean = sm[0], inv = sm[1];
#pragma unroll
    for (int i = 0; i < 4; i++) {
        int c = threadIdx.x + i * 128;
        orow[c] = (v[i] - mean) * inv * w[c] + b[c];
    }
}

// ---------------- generic 128x128x8 SGEMM with epilogues -------------------
// C[M,N] = A[M,K] @ B[K,N] + bias, M multiple of 128, N multiple of 128, K of 8
// epi: 0 = bias; 1 = bias+relu; 2 = bias+add1+add2; 3 = bias+add1
__global__ void sgemm_epi(const float* __restrict__ A, const float* __restrict__ Bm,
                          const float* __restrict__ bias, float* __restrict__ C,
                          int N, int K, int epi,
                          const float* __restrict__ add1, const float* __restrict__ add2) {
    __shared__ float As[8][128];
    __shared__ float Bs[8][128];
    int tid = threadIdx.x;                 // 256
    int rowBase = blockIdx.y * 128;
    int colBase = blockIdx.x * 128;
    int tx = tid & 15, ty = tid >> 4;
    float acc[8][8] = {};
    int ar = tid >> 1;                     // 0..127
    int ak = (tid & 1) * 4;                // 0 or 4
    int bk = tid >> 5;                     // 0..7
    int bc = (tid & 31) * 4;               // 0..124
    const float* Aptr = A + (size_t)(rowBase + ar) * K + ak;
    const float* Bptr = Bm + (size_t)bk * N + colBase + bc;
    for (int k0 = 0; k0 < K; k0 += 8) {
        float4 av = *(const float4*)(Aptr + k0);
        As[ak + 0][ar] = av.x; As[ak + 1][ar] = av.y;
        As[ak + 2][ar] = av.z; As[ak + 3][ar] = av.w;
        float4 bv = *(const float4*)(Bptr + (size_t)k0 * N);
        *(float4*)&Bs[bk][bc] = bv;
        __syncthreads();
#pragma unroll
        for (int kk = 0; kk < 8; kk++) {
            float rm[8], rn[8];
#pragma unroll
            for (int i = 0; i < 8; i++) rm[i] = As[kk][ty * 8 + i];
#pragma unroll
            for (int j = 0; j < 8; j++) rn[j] = Bs[kk][tx * 8 + j];
#pragma unroll
            for (int i = 0; i < 8; i++)
#pragma unroll
                for (int j = 0; j < 8; j++)
                    acc[i][j] += rm[i] * rn[j];
        }
        __syncthreads();
    }
#pragma unroll
    for (int i = 0; i < 8; i++) {
        int r = rowBase + ty * 8 + i;
#pragma unroll
        for (int j = 0; j < 8; j++) {
            int c = colBase + tx * 8 + j;
            float v = acc[i][j] + bias[c];
            if (epi == 1) {
                v = fmaxf(v, 0.f);
            } else if (epi == 2) {
                size_t id2 = (size_t)r * 512 + c;
                v += add1[id2] + add2[id2];
            } else if (epi == 3) {
                size_t id2 = (size_t)r * 512 + c;
                v += add1[id2];
            }
            C[(size_t)r * N + c] = v;
        }
    }
}

// ---------------- FSMN conv1d(512->512, k=11, same pad) --------------------
// out = (conv(v*m) + v*m) * m ;  v lives in g_qkv cols [1024,1536)
__global__ void fsmn_conv(const float* __restrict__ qkv, const float* __restrict__ masks,
                          float* __restrict__ out) {
    __shared__ float As[8][128];
    __shared__ float Bs[8][128];
    int tid = threadIdx.x;
    int rowBase = blockIdx.y * 128;
    int colBase = blockIdx.x * 128;
    int tx = tid & 15, ty = tid >> 4;
    float acc[8][8] = {};
    int ar = tid >> 1;
    int ak = (tid & 1) * 4;
    int bk = tid >> 5;
    int bc = (tid & 31) * 4;
    int grow = rowBase + ar;
    int b = grow / T_;
    int t = grow % T_;
    for (int tap = 0; tap < 11; tap++) {
        int tsrc = t + tap - 5;
        bool valid = (tsrc >= 0 && tsrc < T_);
        const float* Aptr = qkv + ((size_t)(b * T_ + (valid ? tsrc : 0)) * QKVW + 1024 + ak);
        float mval = valid ? masks[b * T_ + tsrc] : 0.f;
        const float* Bptr = g_kw + (size_t)tap * D_ * D_ + (size_t)bk * D_ + colBase + bc;
        for (int k0 = 0; k0 < D_; k0 += 8) {
            float4 av;
            if (valid) av = *(const float4*)(Aptr + k0);
            else       av = make_float4(0.f, 0.f, 0.f, 0.f);
            As[ak + 0][ar] = av.x * mval; As[ak + 1][ar] = av.y * mval;
            As[ak + 2][ar] = av.z * mval; As[ak + 3][ar] = av.w * mval;
            float4 bv = *(const float4*)(Bptr + (size_t)k0 * D_);
            *(float4*)&Bs[bk][bc] = bv;
            __syncthreads();
#pragma unroll
            for (int kk = 0; kk < 8; kk++) {
                float rm[8], rn[8];
#pragma unroll
                for (int i = 0; i < 8; i++) rm[i] = As[kk][ty * 8 + i];
#pragma unroll
                for (int j = 0; j < 8; j++) rn[j] = Bs[kk][tx * 8 + j];
#pragma unroll
                for (int i = 0; i < 8; i++)
#pragma unroll
                    for (int j = 0; j < 8; j++)
                        acc[i][j] += rm[i] * rn[j];
            }
            __syncthreads();
        }
    }
#pragma unroll
    for (int i = 0; i < 8; i++) {
        int r = rowBase + ty * 8 + i;
        float m = masks[r];
#pragma unroll
        for (int j = 0; j < 8; j++) {
            int c = colBase + tx * 8 + j;
            float vv = qkv[(size_t)r * QKVW + 1024 + c];
            out[(size_t)r * D_ + c] = (acc[i][j] + vv * m) * m;
        }
    }
}

// ---------------- attention scores: q @ k^T / sqrt(dk), mask ---------------
__global__ void scores_kernel(const float* __restrict__ qkv, const float* __restrict__ masks,
                              float* __restrict__ scores) {
    int bh = blockIdx.z;
    int b = bh >> 2, h = bh & 3;
    int qbase = blockIdx.y * 32;
    int kbase = blockIdx.x * 32;
    __shared__ float Qs[32][33];
    __shared__ float Ks[32][33];
    int tid = threadIdx.x;                 // 256
    int tx = tid & 15, ty = tid >> 4;
    float acc[2][2] = {};
    const int qoff = h * DK_;
    const int koff = D_ + h * DK_;
    for (int kc = 0; kc < DK_; kc += 32) {
#pragma unroll
        for (int i = 0; i < 4; i++) {
            int e = tid + 256 * i;
            int rr = e >> 5, cc = e & 31;
            int qr = qbase + rr;
            Qs[rr][cc] = (qr < T_) ? qkv[(size_t)(b * T_ + qr) * QKVW + qoff + kc + cc] : 0.f;
            int kr = kbase + rr;
            Ks[rr][cc] = (kr < T_) ? qkv[(size_t)(b * T_ + kr) * QKVW + koff + kc + cc] : 0.f;
        }
        __syncthreads();
#pragma unroll
        for (int kk = 0; kk < 32; kk++) {
            float q0 = Qs[ty * 2 + 0][kk], q1 = Qs[ty * 2 + 1][kk];
            float k0 = Ks[tx * 2 + 0][kk], k1 = Ks[tx * 2 + 1][kk];
            acc[0][0] += q0 * k0; acc[0][1] += q0 * k1;
            acc[1][0] += q1 * k0; acc[1][1] += q1 * k1;
        }
        __syncthreads();
    }
    const float scale = 0.08838834764831845f;  // 1/sqrt(128)
#pragma unroll
    for (int i = 0; i < 2; i++) {
        int r = qbase + ty * 2 + i;
        if (r >= T_) continue;
#pragma unroll
        for (int j = 0; j < 2; j++) {
            int c = kbase + tx * 2 + j;
            if (c >= T_) continue;
            float s = acc[i][j] * scale;
            if (masks[b * T_ + c] <= 0.f) s = -3.0e38f;
            scores[((size_t)bh * T_ + r) * T_ + c] = s;
        }
    }
}

// ---------------- row softmax over 218 (one block per row) -----------------
__global__ void softmax_kernel(float* __restrict__ scores) {
    float* p = scores + (size_t)blockIdx.x * T_;
    int tid = threadIdx.x;                 // 256
    float v = (tid < T_) ? p[tid] : -3.4e38f;
    __shared__ float red[8];
    float m = v;
#pragma unroll
    for (int o = 16; o; o >>= 1) m = fmaxf(m, __shfl_xor_sync(~0u, m, o));
    if ((tid & 31) == 0) red[tid >> 5] = m;
    __syncthreads();
    if (tid < 8) {
        float t = red[tid];
#pragma unroll
        for (int o = 4; o; o >>= 1) t = fmaxf(t, __shfl_xor_sync(0xff, t, o));
        red[tid] = t;
    }
    __syncthreads();
    float mx = red[0];
    float e = (tid < T_) ? expf(v - mx) : 0.f;
    __syncthreads();
    float s = e;
#pragma unroll
    for (int o = 16; o; o >>= 1) s += __shfl_xor_sync(~0u, s, o);
    if ((tid & 31) == 0) red[tid >> 5] = s;
    __syncthreads();
    if (tid < 8) {
        float t = red[tid];
#pragma unroll
        for (int o = 4; o; o >>= 1) t += __shfl_xor_sync(0xff, t, o);
        red[tid] = t;
    }
    __syncthreads();
    float inv = 1.f / red[0];
    if (tid < T_) p[tid] = e * inv;
}

// ---------------- ctx = attn @ v, interleave heads back to [row,512] -------
__global__ void ctx_kernel(const float* __restrict__ scores, const float* __restrict__ qkv,
                           float* __restrict__ ctx) {
    int bh = blockIdx.y;
    int b = bh >> 2, h = bh & 3;
    int t0 = blockIdx.x * 16;
    int nt = T_ - t0; if (nt > 16) nt = 16;
    __shared__ float at[16][T_];           // ~14 KB
    int tid = threadIdx.x;                 // 128
    for (int e = tid; e < 16 * T_; e += 128) {
        int tt = e / T_, k = e % T_;
        at[tt][k] = (tt < nt) ? scores[((size_t)bh * T_ + t0 + tt) * T_ + k] : 0.f;
    }
    __syncthreads();
    float acc[16] = {};
    const int voff = 1024 + h * DK_;
    for (int k = 0; k < T_; k++) {
        float vk = qkv[(size_t)(b * T_ + k) * QKVW + voff + tid];
#pragma unroll
        for (int tt = 0; tt < 16; tt++) acc[tt] += at[tt][k] * vk;
    }
    for (int tt = 0; tt < nt; tt++)
        ctx[(size_t)(b * T_ + t0 + tt) * D_ + h * DK_ + tid] = acc[tt];
}

// ---------------- launch ----------------------------------------------------
extern "C" void kernel_launch(void* const* d_in, const int* in_sizes, int n_in,
                              void* d_out, int out_size) {
    const float* x     = (const float*)d_in[0];
    const float* masks = (const float*)d_in[1];
    const float* ln0_w = (const float*)d_in[2];
    const float* ln0_b = (const float*)d_in[3];
    const float* ln1_w = (const float*)d_in[4];
    const float* ln1_b = (const float*)d_in[5];
    const float* qkv_w = (const float*)d_in[6];
    const float* qkv_b = (const float*)d_in[7];
    const float* out_w = (const float*)d_in[8];
    const float* out_b = (const float*)d_in[9];
    const float* fsmn_w= (const float*)d_in[10];
    const float* w1    = (const float*)d_in[11];
    const float* b1    = (const float*)d_in[12];
    const float* w2    = (const float*)d_in[13];
    const float* b2    = (const float*)d_in[14];
    float* out = (float*)d_out;

    float *h, *qkv, *fsmn, *scores, *ctx, *x1, *mid;
    cudaGetSymbolAddress((void**)&h,      g_h);
    cudaGetSymbolAddress((void**)&qkv,    g_qkv);
    cudaGetSymbolAddress((void**)&fsmn,   g_fsmn);
    cudaGetSymbolAddress((void**)&scores, g_scores);
    cudaGetSymbolAddress((void**)&ctx,    g_ctx);
    cudaGetSymbolAddress((void**)&x1,     g_x1);
    cudaGetSymbolAddress((void**)&mid,    g_mid);

    // fsmn weight transpose -> [tap][din][dout]
    kw_transpose<<<(11 * D_ * D_ + 255) / 256, 256>>>(fsmn_w);

    // LN0
    ln_kernel<<<R_, 128>>>(x, ln0_w, ln0_b, h);

    // QKV: [13952,512] @ [512,1536]
    sgemm_epi<<<dim3(QKVW / 128, R_ / 128), 256>>>(h, qkv_w, qkv_b, qkv,
                                                   QKVW, D_, 0, nullptr, nullptr);

    // FSMN conv branch
    fsmn_conv<<<dim3(D_ / 128, R_ / 128), 256>>>(qkv, masks, fsmn);

    // attention
    scores_kernel<<<dim3(7, 7, B_ * H_), 256>>>(qkv, masks, scores);
    softmax_kernel<<<B_ * H_ * T_, 256>>>(scores);
    ctx_kernel<<<dim3((T_ + 15) / 16, B_ * H_), 128>>>(scores, qkv, ctx);

    // out proj + fsmn + residual -> x1
    sgemm_epi<<<dim3(D_ / 128, R_ / 128), 256>>>(ctx, out_w, out_b, x1,
                                                 D_, D_, 2, fsmn, x);

    // LN1
    ln_kernel<<<R_, 128>>>(x1, ln1_w, ln1_b, h);

    // FFN
    sgemm_epi<<<dim3(2048 / 128, R_ / 128), 256>>>(h, w1, b1, mid,
                                                   2048, D_, 1, nullptr, nullptr);
    sgemm_epi<<<dim3(D_ / 128, R_ / 128), 256>>>(mid, w2, b2, out,
                                                 D_, 2048, 3, x1, nullptr);
    (void)in_sizes; (void)n_in; (void)out_size;
}

// round 3
// speedup vs baseline: 3.4011x; 3.4011x over previous
#include <cuda_runtime.h>
#include <math.h>
#include <cstdint>

#define B_  64
#define T_  218
#define D_  512
#define R_  (B_*T_)      // 13952 = 109*128
#define H_  4
#define DK_ 128
#define QKVW (3*D_)      // 1536

// ---------------- scratch (device globals; no allocations allowed) ----------
__device__ float g_h[R_*D_];
__device__ float g_qkv[R_*QKVW];
__device__ float g_vm[R_*D_];
__device__ float g_fsmn[R_*D_];
__device__ float g_scores[B_*H_*T_*T_];
__device__ float g_ctx[R_*D_];
__device__ float g_x1[R_*D_];
__device__ float g_mid[R_*2048];
__device__ float g_qkv_wt[QKVW*D_];           // [N,K] tf32-rounded
__device__ float g_out_wt[D_*D_];
__device__ float g_w1t[2048*D_];
__device__ float g_w2t[D_*2048];
__device__ float g_kwt[11*D_*D_];             // [tap][dout][din] tf32-rounded

// ---------------- helpers ----------------------------------------------------
__device__ __forceinline__ float rna_tf32(float x) {
    float r; asm("cvt.rna.tf32.f32 %0,%1;" : "=f"(r) : "f"(x)); return r;
}
__device__ __forceinline__ uint32_t smem_u32(const void* p) {
    uint32_t a;
    asm("{ .reg .u64 t; cvta.to.shared.u64 t, %1; cvt.u32.u64 %0, t; }" : "=r"(a) : "l"(p));
    return a;
}
__device__ __forceinline__ void cp16(uint32_t dst, const void* src, bool pred) {
    int sz = pred ? 16 : 0;
    asm volatile("cp.async.ca.shared.global [%0], [%1], 16, %2;"
                 :: "r"(dst), "l"(src), "r"(sz) : "memory");
}
#define CP_COMMIT() asm volatile("cp.async.commit_group;" ::: "memory")
#define CP_WAIT1()  asm volatile("cp.async.wait_group 1;" ::: "memory")
#define CP_WAIT0()  asm volatile("cp.async.wait_group 0;" ::: "memory")

#define MMA(d, a, b0, b1) \
    asm volatile("mma.sync.aligned.m16n8k8.row.col.f32.tf32.tf32.f32 " \
                 "{%0,%1,%2,%3},{%4,%5,%6,%7},{%8,%9},{%0,%1,%2,%3};" \
                 : "+f"((d)[0]), "+f"((d)[1]), "+f"((d)[2]), "+f"((d)[3]) \
                 : "r"((a)[0]), "r"((a)[1]), "r"((a)[2]), "r"((a)[3]), \
                   "r"(b0), "r"(b1))

#define LDW 36                       // padded row width (floats), conflict-free
#define TILEF (128*LDW)              // floats per tile buffer
#define DSMEM_BYTES (4*TILEF*4)      // A0,B0,A1,B1 = 73728 B

// ---------------- weight transpose (+tf32 round) ----------------------------
__global__ void transpose_rna(const float* __restrict__ src, float* __restrict__ dst,
                              int Kd, int Nd) {
    __shared__ float t[32][33];
    int k0 = blockIdx.y * 32, n0 = blockIdx.x * 32;
    int x = threadIdx.x, y = threadIdx.y;   // (32,8)
#pragma unroll
    for (int i = 0; i < 32; i += 8)
        t[y + i][x] = src[(size_t)(k0 + y + i) * Nd + n0 + x];
    __syncthreads();
#pragma unroll
    for (int i = 0; i < 32; i += 8)
        dst[(size_t)(n0 + y + i) * Kd + k0 + x] = rna_tf32(t[x][y + i]);
}

__global__ void kw_transpose(const float* __restrict__ fw) {
    int idx = blockIdx.x * 256 + threadIdx.x;
    if (idx >= 11 * D_ * D_) return;
    int tap = idx / (D_ * D_);
    int rem = idx % (D_ * D_);
    int dout = rem / D_;
    int din = rem % D_;
    g_kwt[idx] = rna_tf32(fw[((size_t)dout * D_ + din) * 11 + tap]);
}

// ---------------- vm = round(v * mask) --------------------------------------
__global__ void vm_kernel(const float* __restrict__ qkv, const float* __restrict__ masks,
                          float* __restrict__ vm) {
    int idx = blockIdx.x * 256 + threadIdx.x;
    int r = idx >> 9, d = idx & 511;
    vm[idx] = rna_tf32(qkv[(size_t)r * QKVW + 1024 + d] * masks[r]);
}

// ---------------- layer norm (tf32-rounded output) --------------------------
__global__ void ln_kernel(const float* __restrict__ x, const float* __restrict__ w,
                          const float* __restrict__ b, float* __restrict__ out) {
    int row = blockIdx.x;
    const float* xr = x + (size_t)row * D_;
    float* orow = out + (size_t)row * D_;
    float v[4];
    float s = 0.f, sq = 0.f;
#pragma unroll
    for (int i = 0; i < 4; i++) {
        v[i] = xr[threadIdx.x + i * 128];
        s += v[i]; sq += v[i] * v[i];
    }
    __shared__ float sm[8];
#pragma unroll
    for (int o = 16; o; o >>= 1) {
        s  += __shfl_xor_sync(~0u, s, o);
        sq += __shfl_xor_sync(~0u, sq, o);
    }
    int lane = threadIdx.x & 31, wid = threadIdx.x >> 5;
    if (lane == 0) { sm[wid] = s; sm[4 + wid] = sq; }
    __syncthreads();
    if (threadIdx.x == 0) {
        float S = sm[0] + sm[1] + sm[2] + sm[3];
        float SQ = sm[4] + sm[5] + sm[6] + sm[7];
        float mean = S * (1.f / D_);
        float var = SQ * (1.f / D_) - mean * mean;
        sm[0] = mean;
        sm[1] = rsqrtf(var + 1e-5f);
    }
    __syncthreads();
    float mean = sm[0], inv = sm[1];
#pragma unroll
    for (int i = 0; i < 4; i++) {
        int c = threadIdx.x + i * 128;
        orow[c] = rna_tf32((v[i] - mean) * inv * w[c] + b[c]);
    }
}

// ---------------- tf32 mma.sync GEMM: C[M,N] = A[M,K] @ Bt[N,K]^T -----------
// epi: 0=bias; 1=bias+relu+round; 2=bias+add1+add2; 3=bias+add1
__global__ void __launch_bounds__(256)
tgemm(const float* __restrict__ A, const float* __restrict__ Bt,
      const float* __restrict__ bias, float* __restrict__ C,
      int N, int K, int epi,
      const float* __restrict__ add1, const float* __restrict__ add2) {
    extern __shared__ float smf[];
    float* Abuf[2] = { smf,             smf + 2 * TILEF };
    float* Bbuf[2] = { smf + TILEF,     smf + 3 * TILEF };
    int tid = threadIdx.x;
    int lane = tid & 31, wid = tid >> 5;
    int wm = (wid & 3) * 32;            // warp row offset in tile
    int wn = (wid >> 2) * 64;           // warp col offset in tile
    int g = lane >> 2, c = lane & 3;
    int rowBase = blockIdx.y * 128, colBase = blockIdx.x * 128;

    // staging slot decomposition: 4 float4 per thread per tile
    int srow[4], sseg[4];
#pragma unroll
    for (int u = 0; u < 4; u++) {
        int f = tid + 256 * u;
        srow[u] = f >> 3;
        sseg[u] = f & 7;
    }

    float acc[2][8][4];
#pragma unroll
    for (int i = 0; i < 2; i++)
#pragma unroll
        for (int j = 0; j < 8; j++)
#pragma unroll
            for (int q = 0; q < 4; q++) acc[i][j][q] = 0.f;

    int nk = K >> 5;
    // stage tile 0
#pragma unroll
    for (int u = 0; u < 4; u++) {
        cp16(smem_u32(Abuf[0] + srow[u] * LDW + sseg[u] * 4),
             A + (size_t)(rowBase + srow[u]) * K + sseg[u] * 4, true);
        cp16(smem_u32(Bbuf[0] + srow[u] * LDW + sseg[u] * 4),
             Bt + (size_t)(colBase + srow[u]) * K + sseg[u] * 4, true);
    }
    CP_COMMIT();

    for (int kt = 0; kt < nk; kt++) {
        int buf = kt & 1;
        if (kt + 1 < nk) {
            int nb = buf ^ 1;
            const float* Ag = A + (size_t)rowBase * K + (kt + 1) * 32;
            const float* Bg = Bt + (size_t)colBase * K + (kt + 1) * 32;
#pragma unroll
            for (int u = 0; u < 4; u++) {
                cp16(smem_u32(Abuf[nb] + srow[u] * LDW + sseg[u] * 4),
                     Ag + (size_t)srow[u] * K + sseg[u] * 4, true);
                cp16(smem_u32(Bbuf[nb] + srow[u] * LDW + sseg[u] * 4),
                     Bg + (size_t)srow[u] * K + sseg[u] * 4, true);
            }
            CP_COMMIT();
            CP_WAIT1();
        } else {
            CP_WAIT0();
        }
        __syncthreads();
        const float* As = Abuf[buf];
        const float* Bs = Bbuf[buf];
#pragma unroll
        for (int ks = 0; ks < 4; ks++) {
            int kk = ks * 8;
            uint32_t a[2][4];
#pragma unroll
            for (int mt = 0; mt < 2; mt++) {
                const float* ap = As + (wm + mt * 16) * LDW + kk;
                a[mt][0] = __float_as_uint(ap[g * LDW + c]);
                a[mt][1] = __float_as_uint(ap[(g + 8) * LDW + c]);
                a[mt][2] = __float_as_uint(ap[g * LDW + c + 4]);
                a[mt][3] = __float_as_uint(ap[(g + 8) * LDW + c + 4]);
            }
#pragma unroll
            for (int nt = 0; nt < 8; nt++) {
                const float* bp = Bs + (wn + nt * 8 + g) * LDW + kk;
                uint32_t b0 = __float_as_uint(bp[c]);
                uint32_t b1 = __float_as_uint(bp[c + 4]);
                MMA(acc[0][nt], a[0], b0, b1);
                MMA(acc[1][nt], a[1], b0, b1);
            }
        }
        __syncthreads();
    }

    // epilogue
#pragma unroll
    for (int mt = 0; mt < 2; mt++) {
#pragma unroll
        for (int nt = 0; nt < 8; nt++) {
            int cb = colBase + wn + nt * 8 + 2 * c;
            float bs0 = bias[cb], bs1 = bias[cb + 1];
#pragma unroll
            for (int half = 0; half < 2; half++) {
                int r = rowBase + wm + mt * 16 + g + half * 8;
                float v0 = acc[mt][nt][half * 2 + 0] + bs0;
                float v1 = acc[mt][nt][half * 2 + 1] + bs1;
                if (epi == 1) {
                    v0 = rna_tf32(fmaxf(v0, 0.f));
                    v1 = rna_tf32(fmaxf(v1, 0.f));
                } else if (epi == 2) {
                    size_t id = (size_t)r * 512 + cb;
                    v0 += add1[id] + add2[id];
                    v1 += add1[id + 1] + add2[id + 1];
                } else if (epi == 3) {
                    size_t id = (size_t)r * 512 + cb;
                    v0 += add1[id];
                    v1 += add1[id + 1];
                }
                *(float2*)(C + (size_t)r * N + cb) = make_float2(v0, v1);
            }
        }
    }
}

// ---------------- FSMN conv via mma.sync: 11 shifted GEMMs ------------------
__global__ void __launch_bounds__(256)
tconv(const float* __restrict__ vm, const float* __restrict__ qkv,
      const float* __restrict__ masks, float* __restrict__ out) {
    extern __shared__ float smf[];
    float* Abuf[2] = { smf,             smf + 2 * TILEF };
    float* Bbuf[2] = { smf + TILEF,     smf + 3 * TILEF };
    int tid = threadIdx.x;
    int lane = tid & 31, wid = tid >> 5;
    int wm = (wid & 3) * 32;
    int wn = (wid >> 2) * 64;
    int g = lane >> 2, c = lane & 3;
    int rowBase = blockIdx.y * 128, colBase = blockIdx.x * 128;

    int srow[4], sseg[4], sb[4], st[4];
#pragma unroll
    for (int u = 0; u < 4; u++) {
        int f = tid + 256 * u;
        srow[u] = f >> 3;
        sseg[u] = f & 7;
        int grow = rowBase + srow[u];
        sb[u] = grow / T_;
        st[u] = grow - sb[u] * T_;
    }

    float acc[2][8][4];
#pragma unroll
    for (int i = 0; i < 2; i++)
#pragma unroll
        for (int j = 0; j < 8; j++)
#pragma unroll
            for (int q = 0; q < 4; q++) acc[i][j][q] = 0.f;

    const int NT = 11 * 16;
    // stage iter 0 (tap 0, kt 0)
#pragma unroll
    for (int u = 0; u < 4; u++) {
        int src = st[u] - 5;
        bool ok = (unsigned)src < (unsigned)T_;
        cp16(smem_u32(Abuf[0] + srow[u] * LDW + sseg[u] * 4),
             vm + ((size_t)(sb[u] * T_ + (ok ? src : 0)) * D_ + sseg[u] * 4), ok);
        cp16(smem_u32(Bbuf[0] + srow[u] * LDW + sseg[u] * 4),
             g_kwt + ((size_t)(colBase + srow[u]) * D_ + sseg[u] * 4), true);
    }
    CP_COMMIT();

    for (int ti = 0; ti < NT; ti++) {
        int buf = ti & 1;
        if (ti + 1 < NT) {
            int nb = buf ^ 1;
            int tap = (ti + 1) >> 4, kt = (ti + 1) & 15;
            const float* Bg = g_kwt + (size_t)tap * D_ * D_ + (size_t)colBase * D_ + kt * 32;
#pragma unroll
            for (int u = 0; u < 4; u++) {
                int src = st[u] + tap - 5;
                bool ok = (unsigned)src < (unsigned)T_;
                cp16(smem_u32(Abuf[nb] + srow[u] * LDW + sseg[u] * 4),
                     vm + ((size_t)(sb[u] * T_ + (ok ? src : 0)) * D_ + kt * 32 + sseg[u] * 4), ok);
                cp16(smem_u32(Bbuf[nb] + srow[u] * LDW + sseg[u] * 4),
                     Bg + (size_t)srow[u] * D_ + sseg[u] * 4, true);
            }
            CP_COMMIT();
            CP_WAIT1();
        } else {
            CP_WAIT0();
        }
        __syncthreads();
        const float* As = Abuf[buf];
        const float* Bs = Bbuf[buf];
#pragma unroll
        for (int ks = 0; ks < 4; ks++) {
            int kk = ks * 8;
            uint32_t a[2][4];
#pragma unroll
            for (int mt = 0; mt < 2; mt++) {
                const float* ap = As + (wm + mt * 16) * LDW + kk;
                a[mt][0] = __float_as_uint(ap[g * LDW + c]);
                a[mt][1] = __float_as_uint(ap[(g + 8) * LDW + c]);
                a[mt][2] = __float_as_uint(ap[g * LDW + c + 4]);
                a[mt][3] = __float_as_uint(ap[(g + 8) * LDW + c + 4]);
            }
#pragma unroll
            for (int nt = 0; nt < 8; nt++) {
                const float* bp = Bs + (wn + nt * 8 + g) * LDW + kk;
                uint32_t b0 = __float_as_uint(bp[c]);
                uint32_t b1 = __float_as_uint(bp[c + 4]);
                MMA(acc[0][nt], a[0], b0, b1);
                MMA(acc[1][nt], a[1], b0, b1);
            }
        }
        __syncthreads();
    }

    // epilogue: out = (acc + v*m) * m
#pragma unroll
    for (int mt = 0; mt < 2; mt++) {
#pragma unroll
        for (int nt = 0; nt < 8; nt++) {
            int cb = colBase + wn + nt * 8 + 2 * c;
#pragma unroll
            for (int half = 0; half < 2; half++) {
                int r = rowBase + wm + mt * 16 + g + half * 8;
                float m = masks[r];
                float v0 = qkv[(size_t)r * QKVW + 1024 + cb];
                float v1 = qkv[(size_t)r * QKVW + 1024 + cb + 1];
                float o0 = (acc[mt][nt][half * 2 + 0] + v0 * m) * m;
                float o1 = (acc[mt][nt][half * 2 + 1] + v1 * m) * m;
                *(float2*)(out + (size_t)r * D_ + cb) = make_float2(o0, o1);
            }
        }
    }
}

// ---------------- attention scores (fp32) -----------------------------------
__global__ void scores_kernel(const float* __restrict__ qkv, const float* __restrict__ masks,
                              float* __restrict__ scores) {
    int bh = blockIdx.z;
    int b = bh >> 2, h = bh & 3;
    int qbase = blockIdx.y * 32;
    int kbase = blockIdx.x * 32;
    __shared__ float Qs[32][33];
    __shared__ float Ks[32][33];
    int tid = threadIdx.x;
    int tx = tid & 15, ty = tid >> 4;
    float acc[2][2] = {};
    const int qoff = h * DK_;
    const int koff = D_ + h * DK_;
    for (int kc = 0; kc < DK_; kc += 32) {
#pragma unroll
        for (int i = 0; i < 4; i++) {
            int e = tid + 256 * i;
            int rr = e >> 5, cc = e & 31;
            int qr = qbase + rr;
            Qs[rr][cc] = (qr < T_) ? qkv[(size_t)(b * T_ + qr) * QKVW + qoff + kc + cc] : 0.f;
            int kr = kbase + rr;
            Ks[rr][cc] = (kr < T_) ? qkv[(size_t)(b * T_ + kr) * QKVW + koff + kc + cc] : 0.f;
        }
        __syncthreads();
#pragma unroll
        for (int kk = 0; kk < 32; kk++) {
            float q0 = Qs[ty * 2 + 0][kk], q1 = Qs[ty * 2 + 1][kk];
            float k0 = Ks[tx * 2 + 0][kk], k1 = Ks[tx * 2 + 1][kk];
            acc[0][0] += q0 * k0; acc[0][1] += q0 * k1;
            acc[1][0] += q1 * k0; acc[1][1] += q1 * k1;
        }
        __syncthreads();
    }
    const float scale = 0.08838834764831845f;
#pragma unroll
    for (int i = 0; i < 2; i++) {
        int r = qbase + ty * 2 + i;
        if (r >= T_) continue;
#pragma unroll
        for (int j = 0; j < 2; j++) {
            int c = kbase + tx * 2 + j;
            if (c >= T_) continue;
            float s = acc[i][j] * scale;
            if (masks[b * T_ + c] <= 0.f) s = -3.0e38f;
            scores[((size_t)bh * T_ + r) * T_ + c] = s;
        }
    }
}

__global__ void softmax_kernel(float* __restrict__ scores) {
    float* p = scores + (size_t)blockIdx.x * T_;
    int tid = threadIdx.x;
    float v = (tid < T_) ? p[tid] : -3.4e38f;
    __shared__ float red[8];
    float m = v;
#pragma unroll
    for (int o = 16; o; o >>= 1) m = fmaxf(m, __shfl_xor_sync(~0u, m, o));
    if ((tid & 31) == 0) red[tid >> 5] = m;
    __syncthreads();
    if (tid < 8) {
        float t = red[tid];
#pragma unroll
        for (int o = 4; o; o >>= 1) t = fmaxf(t, __shfl_xor_sync(0xff, t, o));
        red[tid] = t;
    }
    __syncthreads();
    float mx = red[0];
    float e = (tid < T_) ? expf(v - mx) : 0.f;
    __syncthreads();
    float s = e;
#pragma unroll
    for (int o = 16; o; o >>= 1) s += __shfl_xor_sync(~0u, s, o);
    if ((tid & 31) == 0) red[tid >> 5] = s;
    __syncthreads();
    if (tid < 8) {
        float t = red[tid];
#pragma unroll
        for (int o = 4; o; o >>= 1) t += __shfl_xor_sync(0xff, t, o);
        red[tid] = t;
    }
    __syncthreads();
    float inv = 1.f / red[0];
    if (tid < T_) p[tid] = e * inv;
}

__global__ void ctx_kernel(const float* __restrict__ scores, const float* __restrict__ qkv,
                           float* __restrict__ ctx) {
    int bh = blockIdx.y;
    int b = bh >> 2, h = bh & 3;
    int t0 = blockIdx.x * 16;
    int nt = T_ - t0; if (nt > 16) nt = 16;
    __shared__ float at[16][T_];
    int tid = threadIdx.x;
    for (int e = tid; e < 16 * T_; e += 128) {
        int tt = e / T_, k = e % T_;
        at[tt][k] = (tt < nt) ? scores[((size_t)bh * T_ + t0 + tt) * T_ + k] : 0.f;
    }
    __syncthreads();
    float acc[16] = {};
    const int voff = 1024 + h * DK_;
    for (int k = 0; k < T_; k++) {
        float vk = qkv[(size_t)(b * T_ + k) * QKVW + voff + tid];
#pragma unroll
        for (int tt = 0; tt < 16; tt++) acc[tt] += at[tt][k] * vk;
    }
    for (int tt = 0; tt < nt; tt++)
        ctx[(size_t)(b * T_ + t0 + tt) * D_ + h * DK_ + tid] = rna_tf32(acc[tt]);
}

// ---------------- launch ------------------------------------------------------
extern "C" void kernel_launch(void* const* d_in, const int* in_sizes, int n_in,
                              void* d_out, int out_size) {
    const float* x     = (const float*)d_in[0];
    const float* masks = (const float*)d_in[1];
    const float* ln0_w = (const float*)d_in[2];
    const float* ln0_b = (const float*)d_in[3];
    const float* ln1_w = (const float*)d_in[4];
    const float* ln1_b = (const float*)d_in[5];
    const float* qkv_w = (const float*)d_in[6];
    const float* qkv_b = (const float*)d_in[7];
    const float* out_w = (const float*)d_in[8];
    const float* out_b = (const float*)d_in[9];
    const float* fsmn_w= (const float*)d_in[10];
    const float* w1    = (const float*)d_in[11];
    const float* b1    = (const float*)d_in[12];
    const float* w2    = (const float*)d_in[13];
    const float* b2    = (const float*)d_in[14];
    float* out = (float*)d_out;

    float *h, *qkv, *vm, *fsmn, *scores, *ctx, *x1, *mid;
    float *qkv_wt, *out_wt, *w1t, *w2t;
    cudaGetSymbolAddress((void**)&h,      g_h);
    cudaGetSymbolAddress((void**)&qkv,    g_qkv);
    cudaGetSymbolAddress((void**)&vm,     g_vm);
    cudaGetSymbolAddress((void**)&fsmn,   g_fsmn);
    cudaGetSymbolAddress((void**)&scores, g_scores);
    cudaGetSymbolAddress((void**)&ctx,    g_ctx);
    cudaGetSymbolAddress((void**)&x1,     g_x1);
    cudaGetSymbolAddress((void**)&mid,    g_mid);
    cudaGetSymbolAddress((void**)&qkv_wt, g_qkv_wt);
    cudaGetSymbolAddress((void**)&out_wt, g_out_wt);
    cudaGetSymbolAddress((void**)&w1t,    g_w1t);
    cudaGetSymbolAddress((void**)&w2t,    g_w2t);

    cudaFuncSetAttribute(tgemm, cudaFuncAttributeMaxDynamicSharedMemorySize, DSMEM_BYTES);
    cudaFuncSetAttribute(tconv, cudaFuncAttributeMaxDynamicSharedMemorySize, DSMEM_BYTES);

    // weight prep (tf32-rounded, [N,K] layouts)
    transpose_rna<<<dim3(QKVW / 32, D_ / 32), dim3(32, 8)>>>(qkv_w, qkv_wt, D_, QKVW);
    transpose_rna<<<dim3(D_ / 32, D_ / 32), dim3(32, 8)>>>(out_w, out_wt, D_, D_);
    transpose_rna<<<dim3(2048 / 32, D_ / 32), dim3(32, 8)>>>(w1, w1t, D_, 2048);
    transpose_rna<<<dim3(D_ / 32, 2048 / 32), dim3(32, 8)>>>(w2, w2t, 2048, D_);
    kw_transpose<<<(11 * D_ * D_ + 255) / 256, 256>>>(fsmn_w);

    // LN0 (rounded)
    ln_kernel<<<R_, 128>>>(x, ln0_w, ln0_b, h);

    // QKV
    tgemm<<<dim3(QKVW / 128, R_ / 128), 256, DSMEM_BYTES>>>(h, qkv_wt, qkv_b, qkv,
                                                            QKVW, D_, 0, nullptr, nullptr);
    // masked v
    vm_kernel<<<R_ * D_ / 256, 256>>>(qkv, masks, vm);

    // FSMN conv
    tconv<<<dim3(D_ / 128, R_ / 128), 256, DSMEM_BYTES>>>(vm, qkv, masks, fsmn);

    // attention
    scores_kernel<<<dim3(7, 7, B_ * H_), 256>>>(qkv, masks, scores);
    softmax_kernel<<<B_ * H_ * T_, 256>>>(scores);
    ctx_kernel<<<dim3((T_ + 15) / 16, B_ * H_), 128>>>(scores, qkv, ctx);

    // out proj + fsmn + residual
    tgemm<<<dim3(D_ / 128, R_ / 128), 256, DSMEM_BYTES>>>(ctx, out_wt, out_b, x1,
                                                          D_, D_, 2, fsmn, x);
    // LN1
    ln_kernel<<<R_, 128>>>(x1, ln1_w, ln1_b, h);

    // FFN
    tgemm<<<dim3(2048 / 128, R_ / 128), 256, DSMEM_BYTES>>>(h, w1t, b1, mid,
                                                            2048, D_, 1, nullptr, nullptr);
    tgemm<<<dim3(D_ / 128, R_ / 128), 256, DSMEM_BYTES>>>(mid, w2t, b2, out,
                                                          D_, 2048, 3, x1, nullptr);
    (void)in_sizes; (void)n_in; (void)out_size;
}